// round 6
// baseline (speedup 1.0000x reference)
#include <cuda_runtime.h>
#include <cuda_bf16.h>
#include <cstdint>

#define H 128
#define NMAX 100000
#define TM 128
#define MLP_THREADS 256
#define RSI 144                              // u32 per row, interleaved hi/lo buffer
#define STAGE_OFF (2 * 128 * RSI)            // u32 offset of f32 stage buffer
#define MLP_SMEM (STAGE_OFF * 4 + 128 * 128 * 4)  // 147456 + 65536 = 212992 B

// Scratch (device globals: no allocation allowed)
__device__ __align__(16) float g_x[(size_t)NMAX * H];
__device__ __align__(16) float g_h[(size_t)NMAX * H];
// weight fragments: [layer][warp 8][img 4][nb 2][ks 8][lane 32][2] u32
__device__ __align__(16) uint32_t g_wfrag[3 * 8 * 4 * 2 * 8 * 32 * 2];

__device__ __forceinline__ uint32_t pack_bf16(float x, float y) {
    __nv_bfloat162 t = __floats2bfloat162_rn(x, y);
    return *(uint32_t*)&t;
}
__device__ __forceinline__ uint32_t smem_u32(const void* p) {
    uint32_t a;
    asm("{ .reg .u64 t; cvta.to.shared.u64 t, %1; cvt.u32.u64 %0, t; }" : "=r"(a) : "l"(p));
    return a;
}
__device__ __forceinline__ float silu_fast(float f) {
    float th;
    asm("tanh.approx.f32 %0, %1;" : "=f"(th) : "f"(0.5f * f));
    return f * fmaf(0.5f, th, 0.5f);
}

#define MMA_BF16(c, A0, A1, A2, A3, B0, B1)                                   \
    asm volatile("mma.sync.aligned.m16n8k16.row.col.f32.bf16.bf16.f32 "       \
                 "{%0,%1,%2,%3}, {%4,%5,%6,%7}, {%8,%9}, {%0,%1,%2,%3};"      \
                 : "+f"(c[0]), "+f"(c[1]), "+f"(c[2]), "+f"(c[3])             \
                 : "r"(A0), "r"(A1), "r"(A2), "r"(A3), "r"(B0), "r"(B1));

// interleaved slot for col-pair j (cols 2j,2j+1), hl = 0(hi)/1(lo):
//   slot = (j>>3)*16 + (j&3)*4 + hl*2 + ((j>>2)&1)

// ---------------------------------------------------------------------------
// Weight prep: split W1/W2 (f32 [k][n]) into bf16 hi/lo mma B-fragments,
// laid out exactly in the per-warp register-load order.
// ---------------------------------------------------------------------------
__global__ void wprep_kernel(const float* __restrict__ W1,
                             const float* __restrict__ W2) {
    int idx = blockIdx.x * blockDim.x + threadIdx.x;
    if (idx >= 3 * 8 * 4 * 2 * 8 * 32 * 2) return;
    int r    = idx & 1;
    int lane = (idx >> 1) & 31;
    int ks   = (idx >> 6) & 7;
    int nb   = (idx >> 9) & 1;
    int img  = (idx >> 10) & 3;
    int w    = (idx >> 12) & 7;
    int l    = idx >> 15;
    int gid = lane >> 2, tg = lane & 3;
    int mat = img >> 1, hl = img & 1;
    int n  = w * 16 + nb * 8 + gid;
    int k0 = ks * 16 + tg * 2 + r * 8;
    const float* W = (mat ? W2 : W1) + (size_t)l * H * H;
    float v0 = W[k0 * H + n];
    float v1 = W[(k0 + 1) * H + n];
    __nv_bfloat16 h0 = __float2bfloat16(v0);
    __nv_bfloat16 h1 = __float2bfloat16(v1);
    float o0 = hl ? (v0 - __bfloat162float(h0)) : __bfloat162float(h0);
    float o1 = hl ? (v1 - __bfloat162float(h1)) : __bfloat162float(h1);
    g_wfrag[idx] = pack_bf16(o0, o1);
}

// ---------------------------------------------------------------------------
// Embedding gather
// ---------------------------------------------------------------------------
__global__ void embed_kernel(const float* __restrict__ emb,
                             const int* __restrict__ z,
                             float* __restrict__ x, float* __restrict__ h,
                             int n) {
    int i = blockIdx.x * blockDim.x + threadIdx.x;
    if (i >= n * 32) return;
    int node = i >> 5;
    int c = i & 31;
    float4 v = ((const float4*)emb)[(size_t)z[node] * 32 + c];
    ((float4*)x)[i] = v;
    ((float4*)h)[i] = v;
}

// ---------------------------------------------------------------------------
// Edge/message kernel: one warp per 4 edges (pipelined), lane = 4 channels.
// ---------------------------------------------------------------------------
__global__ void edge_kernel(const float* __restrict__ x,
                            float* __restrict__ h,
                            const float* __restrict__ edge_attr,
                            const int* __restrict__ ei,
                            const float* __restrict__ We,
                            const float* __restrict__ be,
                            int E) {
    __shared__ float Wes[4 * H];
    __shared__ float bes[H];
    int tid = threadIdx.x;
    for (int i = tid; i < 4 * H; i += blockDim.x) Wes[i] = We[i];
    for (int i = tid; i < H; i += blockDim.x) bes[i] = be[i];
    __syncthreads();

    int lane = tid & 31;
    int warp = blockIdx.x * (blockDim.x >> 5) + (tid >> 5);
    int nwarps = gridDim.x * (blockDim.x >> 5);

    float4 w0 = ((const float4*)Wes)[0 * 32 + lane];
    float4 w1 = ((const float4*)Wes)[1 * 32 + lane];
    float4 w2 = ((const float4*)Wes)[2 * 32 + lane];
    float4 w3 = ((const float4*)Wes)[3 * 32 + lane];
    float4 bb = ((const float4*)bes)[lane];

    int stride = nwarps * 4;
    #pragma unroll 1
    for (int e0 = warp * 4; e0 < E; e0 += stride) {
        int ne = E - e0; if (ne > 4) ne = 4;
        int s[4], d[4];
        float4 ea[4], xv[4];
        #pragma unroll
        for (int j = 0; j < 4; j++)
            if (j < ne) { s[j] = ei[e0 + j]; d[j] = ei[E + e0 + j]; }
        #pragma unroll
        for (int j = 0; j < 4; j++)
            if (j < ne) ea[j] = ((const float4*)edge_attr)[e0 + j];
        #pragma unroll
        for (int j = 0; j < 4; j++)
            if (j < ne) xv[j] = ((const float4*)x)[(size_t)s[j] * 32 + lane];
        #pragma unroll
        for (int j = 0; j < 4; j++) {
            if (j >= ne) break;
            float m0 = xv[j].x + bb.x + ea[j].x * w0.x + ea[j].y * w1.x + ea[j].z * w2.x + ea[j].w * w3.x;
            float m1 = xv[j].y + bb.y + ea[j].x * w0.y + ea[j].y * w1.y + ea[j].z * w2.y + ea[j].w * w3.y;
            float m2 = xv[j].z + bb.z + ea[j].x * w0.z + ea[j].y * w1.z + ea[j].z * w2.z + ea[j].w * w3.z;
            float m3 = xv[j].w + bb.w + ea[j].x * w0.w + ea[j].y * w1.w + ea[j].z * w2.w + ea[j].w * w3.w;
            m0 = fmaxf(m0, 0.f); m1 = fmaxf(m1, 0.f);
            m2 = fmaxf(m2, 0.f); m3 = fmaxf(m3, 0.f);
            float* dptr = h + (size_t)d[j] * H + lane * 4;
            asm volatile("red.global.add.v4.f32 [%0], {%1,%2,%3,%4};"
                         :: "l"(dptr), "f"(m0), "f"(m1), "f"(m2), "f"(m3)
                         : "memory");
        }
    }
}

// ---------------------------------------------------------------------------
// Fused 2-layer MLP via mma.sync bf16x3. Interleaved hi/lo smem (LDS.128
// fragments). 2 syncs/tile: convert of next tile is folded into GEMM2 phase.
// ---------------------------------------------------------------------------
__global__ void __launch_bounds__(MLP_THREADS, 1)
mlp_kernel(const float* __restrict__ h_in,
           const uint32_t* __restrict__ wfrag,
           const float* __restrict__ b1, const float* __restrict__ b2,
           float* __restrict__ x_out, float* __restrict__ h_out, int n) {
    extern __shared__ __align__(16) uint32_t sm[];
    uint32_t* HsI = sm;                       // H tile, interleaved hi/lo
    uint32_t* TsI = sm + 128 * RSI;           // T tile, interleaved hi/lo
    float* stage = (float*)(sm + STAGE_OFF);  // 128x128 f32 raw
    uint32_t stage_b = smem_u32(stage);

    int tid = threadIdx.x, w = tid >> 5, lane = tid & 31;
    int gid = lane >> 2, tg = lane & 3;

    // this warp's weight fragments (128 u32)
    uint2 wB[4][2][8];
    {
        const uint2* wp = (const uint2*)wfrag + (size_t)w * 4 * 2 * 8 * 32;
        #pragma unroll
        for (int img = 0; img < 4; img++)
            #pragma unroll
            for (int nb = 0; nb < 2; nb++)
                #pragma unroll
                for (int ks = 0; ks < 8; ks++)
                    wB[img][nb][ks] = wp[(((img * 2) + nb) * 8 + ks) * 32 + lane];
    }
    float2 b1v[2], b2v[2];
    #pragma unroll
    for (int nb = 0; nb < 2; nb++) {
        b1v[nb] = *(const float2*)(b1 + 16 * w + 8 * nb + 2 * tg);
        b2v[nb] = *(const float2*)(b2 + 16 * w + 8 * nb + 2 * tg);
    }

    int ntiles = (n + TM - 1) / TM;

    // conv slot precomputed pieces for this thread's (c4) columns
    // thread i handles float4 at (row = i>>5, c4 = i&31): pairs 2c4, 2c4+1
    // s0 = (c4>>2)*16 + ((2*c4)&3)*4 + ((c4>>1)&1); s1 = s0 + 4

    // ---- prologue: prefetch + convert first tile ----
    {
        int t = blockIdx.x;
        if (t < ntiles) {
            int row0 = t * TM;
            #pragma unroll
            for (int it = 0; it < 16; it++) {
                int i = tid + it * MLP_THREADS;
                int grow = row0 + (i >> 5);
                if (grow < n) {
                    uint32_t sa = stage_b + i * 16;
                    const float* gp = h_in + (size_t)grow * H + (i & 31) * 4;
                    asm volatile("cp.async.ca.shared.global [%0], [%1], 16;"
                                 :: "r"(sa), "l"(gp));
                }
            }
        }
        asm volatile("cp.async.commit_group;");
        asm volatile("cp.async.wait_group 0;" ::: "memory");
        if (t < ntiles) {
            int row0 = t * TM;
            #pragma unroll 4
            for (int it = 0; it < 16; it++) {
                int i = tid + it * MLP_THREADS;
                int row = i >> 5;
                int c4 = i & 31;
                float4 v = make_float4(0.f, 0.f, 0.f, 0.f);
                if (row0 + row < n) v = ((const float4*)stage)[i];
                __nv_bfloat16 hx = __float2bfloat16(v.x), hy = __float2bfloat16(v.y);
                __nv_bfloat16 hz = __float2bfloat16(v.z), hw = __float2bfloat16(v.w);
                int s0 = (c4 >> 2) * 16 + ((2 * c4) & 3) * 4 + ((c4 >> 1) & 1);
                int base = row * RSI;
                HsI[base + s0]     = pack_bf16(__bfloat162float(hx), __bfloat162float(hy));
                HsI[base + s0 + 2] = pack_bf16(v.x - __bfloat162float(hx), v.y - __bfloat162float(hy));
                HsI[base + s0 + 4] = pack_bf16(__bfloat162float(hz), __bfloat162float(hw));
                HsI[base + s0 + 6] = pack_bf16(v.z - __bfloat162float(hz), v.w - __bfloat162float(hw));
            }
        }
        __syncthreads();
    }

    for (int t = blockIdx.x; t < ntiles; t += gridDim.x) {
        int row0 = t * TM;
        int tn = t + gridDim.x;
        int row0n = tn * TM;

        // ---- phase A: issue prefetch(next tile), GEMM1 + epi1 ----
        if (tn < ntiles) {
            #pragma unroll
            for (int it = 0; it < 16; it++) {
                int i = tid + it * MLP_THREADS;
                int grow = row0n + (i >> 5);
                if (grow < n) {
                    uint32_t sa = stage_b + i * 16;
                    const float* gp = h_in + (size_t)grow * H + (i & 31) * 4;
                    asm volatile("cp.async.ca.shared.global [%0], [%1], 16;"
                                 :: "r"(sa), "l"(gp));
                }
            }
        }
        asm volatile("cp.async.commit_group;");

        #pragma unroll 1
        for (int mb = 0; mb < 8; mb++) {
            float acc[2][4] = {{0.f, 0.f, 0.f, 0.f}, {0.f, 0.f, 0.f, 0.f}};
            int ra = (mb * 16 + gid) * RSI + tg * 4;
            int rb = ra + 8 * RSI;
            #pragma unroll
            for (int ks = 0; ks < 8; ks++) {
                uint4 qa = *(const uint4*)(HsI + ra + ks * 16);
                uint4 qb = *(const uint4*)(HsI + rb + ks * 16);
                #pragma unroll
                for (int nb = 0; nb < 2; nb++) {
                    uint2 bh = wB[0][nb][ks];
                    uint2 bl = wB[1][nb][ks];
                    MMA_BF16(acc[nb], qa.x, qb.x, qa.y, qb.y, bh.x, bh.y);
                    MMA_BF16(acc[nb], qa.z, qb.z, qa.w, qb.w, bh.x, bh.y);
                    MMA_BF16(acc[nb], qa.x, qb.x, qa.y, qb.y, bl.x, bl.y);
                }
            }
            // epi1: bias + silu + split; store as 4x STS.64 (nb pairs adjacent)
            float f0a = silu_fast(acc[0][0] + b1v[0].x);
            float f1a = silu_fast(acc[0][1] + b1v[0].y);
            float f0b = silu_fast(acc[1][0] + b1v[1].x);
            float f1b = silu_fast(acc[1][1] + b1v[1].y);
            float f2a = silu_fast(acc[0][2] + b1v[0].x);
            float f3a = silu_fast(acc[0][3] + b1v[0].y);
            float f2b = silu_fast(acc[1][2] + b1v[1].x);
            float f3b = silu_fast(acc[1][3] + b1v[1].y);
            __nv_bfloat16 h0a = __float2bfloat16(f0a), h1a = __float2bfloat16(f1a);
            __nv_bfloat16 h0b = __float2bfloat16(f0b), h1b = __float2bfloat16(f1b);
            __nv_bfloat16 h2a = __float2bfloat16(f2a), h3a = __float2bfloat16(f3a);
            __nv_bfloat16 h2b = __float2bfloat16(f2b), h3b = __float2bfloat16(f3b);
            int sa = (mb * 16 + gid) * RSI + w * 16 + tg * 4;
            int sb = sa + 8 * RSI;
            uint2 hiA, loA, hiB, loB;
            hiA.x = pack_bf16(__bfloat162float(h0a), __bfloat162float(h1a));
            hiA.y = pack_bf16(__bfloat162float(h0b), __bfloat162float(h1b));
            loA.x = pack_bf16(f0a - __bfloat162float(h0a), f1a - __bfloat162float(h1a));
            loA.y = pack_bf16(f0b - __bfloat162float(h0b), f1b - __bfloat162float(h1b));
            hiB.x = pack_bf16(__bfloat162float(h2a), __bfloat162float(h3a));
            hiB.y = pack_bf16(__bfloat162float(h2b), __bfloat162float(h3b));
            loB.x = pack_bf16(f2a - __bfloat162float(h2a), f3a - __bfloat162float(h3a));
            loB.y = pack_bf16(f2b - __bfloat162float(h2b), f3b - __bfloat162float(h3b));
            *(uint2*)(TsI + sa)     = hiA;
            *(uint2*)(TsI + sa + 2) = loA;
            *(uint2*)(TsI + sb)     = hiB;
            *(uint2*)(TsI + sb + 2) = loB;
        }
        __syncthreads();

        // ---- phase B: GEMM2 interleaved with convert(next tile) ----
        asm volatile("cp.async.wait_group 0;" ::: "memory");

        #pragma unroll 1
        for (int mb = 0; mb < 8; mb++) {
            float acc[2][4] = {{0.f, 0.f, 0.f, 0.f}, {0.f, 0.f, 0.f, 0.f}};
            int ra = (mb * 16 + gid) * RSI + tg * 4;
            int rb = ra + 8 * RSI;
            #pragma unroll
            for (int ks = 0; ks < 8; ks++) {
                uint4 qa = *(const uint4*)(TsI + ra + ks * 16);
                uint4 qb = *(const uint4*)(TsI + rb + ks * 16);
                #pragma unroll
                for (int nb = 0; nb < 2; nb++) {
                    uint2 bh = wB[2][nb][ks];
                    uint2 bl = wB[3][nb][ks];
                    MMA_BF16(acc[nb], qa.x, qb.x, qa.y, qb.y, bh.x, bh.y);
                    MMA_BF16(acc[nb], qa.z, qb.z, qa.w, qb.w, bh.x, bh.y);
                    MMA_BF16(acc[nb], qa.x, qb.x, qa.y, qb.y, bl.x, bl.y);
                }
            }
            // conv chunk for next tile (2 sub-iters per mb), overlaps MMAs above
            if (tn < ntiles) {
                #pragma unroll
                for (int sub = 0; sub < 2; sub++) {
                    int i = tid + (mb * 2 + sub) * MLP_THREADS;
                    int row = i >> 5;
                    int c4 = i & 31;
                    float4 v = make_float4(0.f, 0.f, 0.f, 0.f);
                    if (row0n + row < n) v = ((const float4*)stage)[i];
                    __nv_bfloat16 hx = __float2bfloat16(v.x), hy = __float2bfloat16(v.y);
                    __nv_bfloat16 hz = __float2bfloat16(v.z), hw = __float2bfloat16(v.w);
                    int s0 = (c4 >> 2) * 16 + ((2 * c4) & 3) * 4 + ((c4 >> 1) & 1);
                    int base = row * RSI;
                    HsI[base + s0]     = pack_bf16(__bfloat162float(hx), __bfloat162float(hy));
                    HsI[base + s0 + 2] = pack_bf16(v.x - __bfloat162float(hx), v.y - __bfloat162float(hy));
                    HsI[base + s0 + 4] = pack_bf16(__bfloat162float(hz), __bfloat162float(hw));
                    HsI[base + s0 + 6] = pack_bf16(v.z - __bfloat162float(hz), v.w - __bfloat162float(hw));
                }
            }
            // epi2: bias + store to gmem
            int r0 = row0 + mb * 16 + gid;
            int r1 = r0 + 8;
            #pragma unroll
            for (int nb = 0; nb < 2; nb++) {
                int col = 16 * w + 8 * nb + 2 * tg;
                if (r0 < n) {
                    float2 o0 = make_float2(acc[nb][0] + b2v[nb].x,
                                            acc[nb][1] + b2v[nb].y);
                    *(float2*)(x_out + (size_t)r0 * H + col) = o0;
                    if (h_out) *(float2*)(h_out + (size_t)r0 * H + col) = o0;
                }
                if (r1 < n) {
                    float2 o1 = make_float2(acc[nb][2] + b2v[nb].x,
                                            acc[nb][3] + b2v[nb].y);
                    *(float2*)(x_out + (size_t)r1 * H + col) = o1;
                    if (h_out) *(float2*)(h_out + (size_t)r1 * H + col) = o1;
                }
            }
        }
        __syncthreads();
    }
}

// batch_vec -> float tail of the output
__global__ void batch_kernel(const int* __restrict__ bv, float* __restrict__ out, int n) {
    int i = blockIdx.x * blockDim.x + threadIdx.x;
    if (i < n) out[i] = (float)bv[i];
}

extern "C" void kernel_launch(void* const* d_in, const int* in_sizes, int n_in,
                              void* d_out, int out_size) {
    const float* emb       = (const float*)d_in[0];
    const float* We        = (const float*)d_in[1];
    const float* be        = (const float*)d_in[2];
    const float* W1        = (const float*)d_in[3];
    const float* b1        = (const float*)d_in[4];
    const float* W2        = (const float*)d_in[5];
    const float* b2        = (const float*)d_in[6];
    const float* edge_attr = (const float*)d_in[7];
    const int*   z         = (const int*)d_in[8];
    const int*   ei        = (const int*)d_in[9];
    const int*   bv        = (const int*)d_in[10];

    int n = in_sizes[8];
    int E = in_sizes[9] / 2;
    float* out = (float*)d_out;

    float *gx, *gh;
    uint32_t* gwf;
    cudaGetSymbolAddress((void**)&gx, g_x);
    cudaGetSymbolAddress((void**)&gh, g_h);
    cudaGetSymbolAddress((void**)&gwf, g_wfrag);

    cudaFuncSetAttribute(mlp_kernel, cudaFuncAttributeMaxDynamicSharedMemorySize,
                         MLP_SMEM);

    wprep_kernel<<<(3 * 8 * 4 * 2 * 8 * 32 * 2 + 255) / 256, 256>>>(W1, W2);
    embed_kernel<<<(n * 32 + 255) / 256, 256>>>(emb, z, gx, gh, n);

    for (int l = 0; l < 3; l++) {
        edge_kernel<<<4096, 256>>>(gx, gh, edge_attr, ei,
                                   We + (size_t)l * 4 * H, be + (size_t)l * H, E);
        bool last = (l == 2);
        mlp_kernel<<<148, MLP_THREADS, MLP_SMEM>>>(
            gh,
            gwf + (size_t)l * 8 * 4 * 2 * 8 * 32 * 2,
            b1 + (size_t)l * H, b2 + (size_t)l * H,
            last ? out : gx,
            last ? nullptr : gh,
            n);
    }

    if (out_size >= n * H + n) {
        batch_kernel<<<(n + 255) / 256, 256>>>(bv, out + (size_t)n * H, n);
    }
}